// round 11
// baseline (speedup 1.0000x reference)
#include <cuda_runtime.h>
#include <cuda_bf16.h>

// Problem constants (fixed by the reference: pc (4,4096,3), mask (4,4096,30))
#define BQ_B 4
#define BQ_N 4096
#define BQ_C 30
#define BQ_K 16
#define BQ_R2 0.04f

#define WARPS_PER_BLOCK 8
#define NUM_QUERIES (BQ_B * BQ_N)                       // 16384
#define NUM_BLOCKS (NUM_QUERIES / WARPS_PER_BLOCK)      // 2048

__device__ float    g_partials[NUM_BLOCKS];
__device__ unsigned g_ticket = 0;   // reset by the last block each launch

__global__ __launch_bounds__(WARPS_PER_BLOCK * 32)
void ballq_loss_kernel(const float* __restrict__ pc,
                       const float* __restrict__ mask,
                       float* __restrict__ out) {
    const int warp = threadIdx.x >> 5;
    const int lane = threadIdx.x & 31;
    const int q = blockIdx.x * WARPS_PER_BLOCK + warp;   // query id, 0..16383
    const int b = q >> 12;                               // q / 4096
    const int n = q & (BQ_N - 1);                        // q % 4096

    const float* __restrict__ pcb = pc + (size_t)b * BQ_N * 3;

    // Query point (broadcast load, same address across warp)
    const float qx = pcb[n * 3 + 0];
    const float qy = pcb[n * 3 + 1];
    const float qz = pcb[n * 3 + 2];
    const float qsq = qx * qx + qy * qy + qz * qz;

    const unsigned lanemask_lt = (1u << lane) - 1u;

    __shared__ int sidx[WARPS_PER_BLOCK][BQ_K];

    // ---- Ball-query scan: first K indices (index order) with d2 < R2 ----
    // Lane L owns candidates base+4L .. base+4L+3 (48 contiguous bytes ->
    // 3 LDG.128 per lane per 128 candidates).
    // Emit: ballot-rank parallel writes, NO shuffles. Rank of lane L's hits
    // = hits in lower lanes (all have smaller indices, lane-major layout)
    // + within-lane j order. d2 = qsq + msq - 2*dot matches the reference's
    // algebraic form so boundary rounding errors correlate with it.
    const float4* __restrict__ pl =
        (const float4*)(pcb + (size_t)lane * 12);        // 48B per lane

    int cnt = 0;  // uniform across the warp (may exceed BQ_K transiently)
    for (int base = 0; base < BQ_N && cnt < BQ_K; base += 128, pl += 96) {
        // 3 wide loads cover this lane's 4 candidates (N % 128 == 0)
        const float4 fa = pl[0];
        const float4 fb = pl[1];
        const float4 fc = pl[2];

        // Unpack candidate xyz (c0..c3 ascending index within lane)
        const float x0 = fa.x, y0 = fa.y, z0 = fa.z;
        const float x1 = fa.w, y1 = fb.x, z1 = fb.y;
        const float x2 = fb.z, y2 = fb.w, z2 = fc.x;
        const float x3 = fc.y, y3 = fc.z, z3 = fc.w;

        unsigned nib = 0u;
        {
            const float msq = x0 * x0 + y0 * y0 + z0 * z0;
            const float dot = qx * x0 + qy * y0 + qz * z0;
            if (qsq + msq - 2.0f * dot < BQ_R2) nib |= 1u;
        }
        {
            const float msq = x1 * x1 + y1 * y1 + z1 * z1;
            const float dot = qx * x1 + qy * y1 + qz * z1;
            if (qsq + msq - 2.0f * dot < BQ_R2) nib |= 2u;
        }
        {
            const float msq = x2 * x2 + y2 * y2 + z2 * z2;
            const float dot = qx * x2 + qy * y2 + qz * z2;
            if (qsq + msq - 2.0f * dot < BQ_R2) nib |= 4u;
        }
        {
            const float msq = x3 * x3 + y3 * y3 + z3 * z3;
            const float dot = qx * x3 + qy * y3 + qz * z3;
            if (qsq + msq - 2.0f * dot < BQ_R2) nib |= 8u;
        }

        // 4 independent ballots (pipeline; no serial shfl chain)
        const unsigned b0 = __ballot_sync(0xffffffffu, nib & 1u);
        const unsigned b1 = __ballot_sync(0xffffffffu, nib & 2u);
        const unsigned b2 = __ballot_sync(0xffffffffu, nib & 4u);
        const unsigned b3 = __ballot_sync(0xffffffffu, nib & 8u);

        // Exclusive rank of this lane's hits among lower lanes' hits
        const int excl = __popc(b0 & lanemask_lt) + __popc(b1 & lanemask_lt)
                       + __popc(b2 & lanemask_lt) + __popc(b3 & lanemask_lt);
        const int total = __popc(b0) + __popc(b1) + __popc(b2) + __popc(b3);

        // Each hit lane writes its own hits, ascending j (ascending index)
        if (nib) {
            int s = cnt + excl;
            unsigned nb = nib;
            const int bi = base + lane * 4;
            do {
                const int jj = __ffs(nb) - 1;
                if (s < BQ_K) sidx[warp][s] = bi + jj;
                s++;
                nb &= nb - 1u;
            } while (nb);
        }
        cnt += total;   // uniform
    }
    __syncwarp();
    // Pad remaining slots with the first found index (cnt >= 1: self hit)
    if (lane == 0) {
        const int f = sidx[warp][0];
        for (int j = (cnt < BQ_K ? cnt : BQ_K); j < BQ_K; j++) sidx[warp][j] = f;
    }
    __syncwarp();

    // ---- Loss: lane c handles channel c (c < 30); neighbor rows coalesced ----
    float acc = 0.0f;
    if (lane < BQ_C) {
        const float* __restrict__ mb = mask + (size_t)b * BQ_N * BQ_C;
        const float mq = mb[n * BQ_C + lane];
#pragma unroll
        for (int j = 0; j < BQ_K; j++) {
            const int id = sidx[warp][j];
            acc += fabsf(mq - mb[id * BQ_C + lane]);
        }
    }
    // Warp reduce (lanes 30,31 contribute 0)
#pragma unroll
    for (int off = 16; off; off >>= 1)
        acc += __shfl_down_sync(0xffffffffu, acc, off);

    __shared__ float wl[WARPS_PER_BLOCK];
    if (lane == 0) wl[warp] = acc;
    __syncthreads();

    // Per-block partial in fixed order (no float atomics -> deterministic)
    __shared__ bool is_last;
    if (threadIdx.x == 0) {
        float s = 0.0f;
#pragma unroll
        for (int w2 = 0; w2 < WARPS_PER_BLOCK; w2++) s += wl[w2];
        g_partials[blockIdx.x] = s;
        __threadfence();                                  // publish partial
        unsigned t = atomicAdd(&g_ticket, 1u);            // int ticket only
        is_last = (t == NUM_BLOCKS - 1);
    }
    __syncthreads();

    // ---- Fused final reduction: last block, fixed order, deterministic ----
    if (is_last) {
        __shared__ float sh[256];
        float s = 0.0f;
        for (int i = threadIdx.x; i < NUM_BLOCKS; i += 256)
            s += g_partials[i];
        sh[threadIdx.x] = s;
        __syncthreads();
#pragma unroll
        for (int off = 128; off; off >>= 1) {
            if (threadIdx.x < off) sh[threadIdx.x] += sh[threadIdx.x + off];
            __syncthreads();
        }
        if (threadIdx.x == 0) {
            out[0] = sh[0] * (1.0f / ((float)BQ_K * (float)NUM_QUERIES));
            g_ticket = 0;                                 // reset for next replay
        }
    }
}

extern "C" void kernel_launch(void* const* d_in, const int* in_sizes, int n_in,
                              void* d_out, int out_size) {
    const float* pc   = (const float*)d_in[0];   // (4, 4096, 3) float32
    const float* mask = (const float*)d_in[1];   // (4, 4096, 30) float32
    float* out = (float*)d_out;                  // scalar float32

    ballq_loss_kernel<<<NUM_BLOCKS, WARPS_PER_BLOCK * 32>>>(pc, mask, out);
}

// round 12
// speedup vs baseline: 1.0088x; 1.0088x over previous
#include <cuda_runtime.h>
#include <cuda_bf16.h>

// Problem constants (fixed by the reference: pc (4,4096,3), mask (4,4096,30))
#define BQ_B 4
#define BQ_N 4096
#define BQ_C 30
#define BQ_K 16
#define BQ_R2 0.04f

#define WARPS_PER_BLOCK 8
#define NUM_QUERIES (BQ_B * BQ_N)                       // 16384
#define NUM_BLOCKS (NUM_QUERIES / WARPS_PER_BLOCK)      // 2048

__device__ float    g_partials[NUM_BLOCKS];
__device__ unsigned g_ticket = 0;   // reset by the last block each launch

__global__ __launch_bounds__(WARPS_PER_BLOCK * 32)
void ballq_loss_kernel(const float* __restrict__ pc,
                       const float* __restrict__ mask,
                       float* __restrict__ out) {
    const int warp = threadIdx.x >> 5;
    const int lane = threadIdx.x & 31;
    const int q = blockIdx.x * WARPS_PER_BLOCK + warp;   // query id, 0..16383
    const int b = q >> 12;                               // q / 4096
    const int n = q & (BQ_N - 1);                        // q % 4096

    const float* __restrict__ pcb = pc + (size_t)b * BQ_N * 3;

    // Query point (broadcast load, same address across warp)
    const float qx = pcb[n * 3 + 0];
    const float qy = pcb[n * 3 + 1];
    const float qz = pcb[n * 3 + 2];
    const float qsq = qx * qx + qy * qy + qz * qz;

    const unsigned lanemask_lt = (1u << lane) - 1u;

    __shared__ int sidx[WARPS_PER_BLOCK][BQ_K];

    // ---- Ball-query scan: first K indices (index order) with d2 < R2 ----
    // Lane L owns candidates base+4L .. base+4L+3 (48 contiguous bytes ->
    // 3 LDG.128 per lane per 128 candidates).
    // 2-stage pipeline: next block's 3 wide loads are issued BEFORE the
    // current block's d2/ballot/emit, so load latency overlaps compute.
    // Emit: ballot-rank parallel writes (no shuffles); rank of lane L's hits
    // = hits in lower lanes + within-lane j order (lane-major = index order).
    // d2 = qsq + msq - 2*dot matches the reference's algebraic form so
    // boundary rounding errors correlate with it.
    const float4* __restrict__ pl =
        (const float4*)(pcb + (size_t)lane * 12);        // 48B per lane

    float4 fa = pl[0];
    float4 fb = pl[1];
    float4 fc = pl[2];

    int cnt = 0;  // uniform across the warp (may exceed BQ_K transiently)
    for (int base = 0; base < BQ_N && cnt < BQ_K; base += 128) {
        // Prefetch next block (clamped re-read of current on last iter)
        pl += 96;
        const float4* __restrict__ pn = (base + 128 < BQ_N) ? pl : (pl - 96);
        const float4 na = pn[0];
        const float4 nb4 = pn[1];
        const float4 nc = pn[2];

        // Unpack current candidates (c0..c3 ascending index within lane)
        const float x0 = fa.x, y0 = fa.y, z0 = fa.z;
        const float x1 = fa.w, y1 = fb.x, z1 = fb.y;
        const float x2 = fb.z, y2 = fb.w, z2 = fc.x;
        const float x3 = fc.y, y3 = fc.z, z3 = fc.w;

        unsigned nib = 0u;
        {
            const float msq = x0 * x0 + y0 * y0 + z0 * z0;
            const float dot = qx * x0 + qy * y0 + qz * z0;
            if (qsq + msq - 2.0f * dot < BQ_R2) nib |= 1u;
        }
        {
            const float msq = x1 * x1 + y1 * y1 + z1 * z1;
            const float dot = qx * x1 + qy * y1 + qz * z1;
            if (qsq + msq - 2.0f * dot < BQ_R2) nib |= 2u;
        }
        {
            const float msq = x2 * x2 + y2 * y2 + z2 * z2;
            const float dot = qx * x2 + qy * y2 + qz * z2;
            if (qsq + msq - 2.0f * dot < BQ_R2) nib |= 4u;
        }
        {
            const float msq = x3 * x3 + y3 * y3 + z3 * z3;
            const float dot = qx * x3 + qy * y3 + qz * z3;
            if (qsq + msq - 2.0f * dot < BQ_R2) nib |= 8u;
        }

        // 4 independent ballots (pipeline; no serial shfl chain)
        const unsigned b0 = __ballot_sync(0xffffffffu, nib & 1u);
        const unsigned b1 = __ballot_sync(0xffffffffu, nib & 2u);
        const unsigned b2 = __ballot_sync(0xffffffffu, nib & 4u);
        const unsigned b3 = __ballot_sync(0xffffffffu, nib & 8u);

        // Exclusive rank of this lane's hits among lower lanes' hits
        const int excl = __popc(b0 & lanemask_lt) + __popc(b1 & lanemask_lt)
                       + __popc(b2 & lanemask_lt) + __popc(b3 & lanemask_lt);
        const int total = __popc(b0) + __popc(b1) + __popc(b2) + __popc(b3);

        // Each hit lane writes its own hits, ascending j (ascending index)
        if (nib) {
            int s = cnt + excl;
            unsigned nb = nib;
            const int bi = base + lane * 4;
            do {
                const int jj = __ffs(nb) - 1;
                if (s < BQ_K) sidx[warp][s] = bi + jj;
                s++;
                nb &= nb - 1u;
            } while (nb);
        }
        cnt += total;   // uniform

        // Rotate pipeline registers
        fa = na; fb = nb4; fc = nc;
    }
    __syncwarp();
    // Pad remaining slots with the first found index (cnt >= 1: self hit)
    if (lane == 0) {
        const int f = sidx[warp][0];
        for (int j = (cnt < BQ_K ? cnt : BQ_K); j < BQ_K; j++) sidx[warp][j] = f;
    }
    __syncwarp();

    // ---- Loss: lane c handles channel c (c < 30); neighbor rows coalesced ----
    float acc = 0.0f;
    if (lane < BQ_C) {
        const float* __restrict__ mb = mask + (size_t)b * BQ_N * BQ_C;
        const float mq = mb[n * BQ_C + lane];
#pragma unroll
        for (int j = 0; j < BQ_K; j++) {
            const int id = sidx[warp][j];
            acc += fabsf(mq - mb[id * BQ_C + lane]);
        }
    }
    // Warp reduce (lanes 30,31 contribute 0)
#pragma unroll
    for (int off = 16; off; off >>= 1)
        acc += __shfl_down_sync(0xffffffffu, acc, off);

    __shared__ float wl[WARPS_PER_BLOCK];
    if (lane == 0) wl[warp] = acc;
    __syncthreads();

    // Per-block partial in fixed order (no float atomics -> deterministic)
    __shared__ bool is_last;
    if (threadIdx.x == 0) {
        float s = 0.0f;
#pragma unroll
        for (int w2 = 0; w2 < WARPS_PER_BLOCK; w2++) s += wl[w2];
        g_partials[blockIdx.x] = s;
        __threadfence();                                  // publish partial
        unsigned t = atomicAdd(&g_ticket, 1u);            // int ticket only
        is_last = (t == NUM_BLOCKS - 1);
    }
    __syncthreads();

    // ---- Fused final reduction: last block, fixed order, deterministic ----
    if (is_last) {
        __shared__ float sh[256];
        float s = 0.0f;
        for (int i = threadIdx.x; i < NUM_BLOCKS; i += 256)
            s += g_partials[i];
        sh[threadIdx.x] = s;
        __syncthreads();
#pragma unroll
        for (int off = 128; off; off >>= 1) {
            if (threadIdx.x < off) sh[threadIdx.x] += sh[threadIdx.x + off];
            __syncthreads();
        }
        if (threadIdx.x == 0) {
            out[0] = sh[0] * (1.0f / ((float)BQ_K * (float)NUM_QUERIES));
            g_ticket = 0;                                 // reset for next replay
        }
    }
}

extern "C" void kernel_launch(void* const* d_in, const int* in_sizes, int n_in,
                              void* d_out, int out_size) {
    const float* pc   = (const float*)d_in[0];   // (4, 4096, 3) float32
    const float* mask = (const float*)d_in[1];   // (4, 4096, 30) float32
    float* out = (float*)d_out;                  // scalar float32

    ballq_loss_kernel<<<NUM_BLOCKS, WARPS_PER_BLOCK * 32>>>(pc, mask, out);
}

// round 15
// speedup vs baseline: 1.0110x; 1.0022x over previous
#include <cuda_runtime.h>
#include <cuda_bf16.h>

// Problem constants (fixed by the reference: pc (4,4096,3), mask (4,4096,30))
#define BQ_B 4
#define BQ_N 4096
#define BQ_C 30
#define BQ_K 16
#define BQ_R2 0.04f

#define WARPS_PER_BLOCK 8
#define NUM_QUERIES (BQ_B * BQ_N)                       // 16384
#define NUM_TASKS (NUM_QUERIES / 2)                     // 8192 warp-tasks
#define NUM_BLOCKS (NUM_TASKS / WARPS_PER_BLOCK)        // 1024

__device__ float    g_partials[NUM_BLOCKS];
__device__ unsigned g_ticket = 0;   // reset by the last block each launch

__global__ __launch_bounds__(WARPS_PER_BLOCK * 32)
void ballq_loss_kernel(const float* __restrict__ pc,
                       const float* __restrict__ mask,
                       float* __restrict__ out) {
    const int warp = threadIdx.x >> 5;
    const int lane = threadIdx.x & 31;
    const int t = blockIdx.x * WARPS_PER_BLOCK + warp;   // task id, 0..8191
    const int b  = t >> 11;                              // batch (2t >> 12)
    const int nA = (2 * t) & (BQ_N - 1);                 // query A row
    const int nB = nA + 1;                               // query B row (same batch)

    const float* __restrict__ pcb = pc + (size_t)b * BQ_N * 3;

    // Two query points (broadcast loads)
    const float qAx = pcb[nA * 3 + 0], qAy = pcb[nA * 3 + 1], qAz = pcb[nA * 3 + 2];
    const float qBx = pcb[nB * 3 + 0], qBy = pcb[nB * 3 + 1], qBz = pcb[nB * 3 + 2];
    const float qAsq = qAx * qAx + qAy * qAy + qAz * qAz;
    const float qBsq = qBx * qBx + qBy * qBy + qBz * qBz;

    const unsigned lanemask_lt = (1u << lane) - 1u;

    __shared__ int sidx[WARPS_PER_BLOCK][2][BQ_K];

    // ---- Dual ball-query scan: one candidate stream, two chains ----
    // Lane L owns candidates base+4L..base+4L+3 (48B -> 3 LDG.128 per 128).
    // Both queries test the SAME loaded candidates; the two ballot/emit
    // chains are independent -> 2x per-warp ILP. Emit is ballot-rank
    // parallel (no shuffles), lane-major = ascending index order.
    // d2 = qsq + msq - 2*dot matches the reference's algebraic form so
    // boundary rounding errors correlate with it.
    const float4* __restrict__ pl =
        (const float4*)(pcb + (size_t)lane * 12);        // 48B per lane

    int cntA = 0, cntB = 0;  // uniform (may exceed BQ_K transiently)
    for (int base = 0; base < BQ_N && (cntA < BQ_K || cntB < BQ_K);
         base += 128, pl += 96) {
        const float4 fa = pl[0];
        const float4 fb = pl[1];
        const float4 fc = pl[2];

        // Candidate xyz (c0..c3 ascending index within lane)
        const float x0 = fa.x, y0 = fa.y, z0 = fa.z;
        const float x1 = fa.w, y1 = fb.x, z1 = fb.y;
        const float x2 = fb.z, y2 = fb.w, z2 = fc.x;
        const float x3 = fc.y, y3 = fc.z, z3 = fc.w;

        const float m0 = x0 * x0 + y0 * y0 + z0 * z0;
        const float m1 = x1 * x1 + y1 * y1 + z1 * z1;
        const float m2 = x2 * x2 + y2 * y2 + z2 * z2;
        const float m3 = x3 * x3 + y3 * y3 + z3 * z3;

        const int bi = base + lane * 4;

        // ---- Chain A ----
        if (cntA < BQ_K) {                               // uniform predicate
            unsigned nib = 0u;
            if (qAsq + m0 - 2.0f * (qAx * x0 + qAy * y0 + qAz * z0) < BQ_R2) nib |= 1u;
            if (qAsq + m1 - 2.0f * (qAx * x1 + qAy * y1 + qAz * z1) < BQ_R2) nib |= 2u;
            if (qAsq + m2 - 2.0f * (qAx * x2 + qAy * y2 + qAz * z2) < BQ_R2) nib |= 4u;
            if (qAsq + m3 - 2.0f * (qAx * x3 + qAy * y3 + qAz * z3) < BQ_R2) nib |= 8u;

            const unsigned b0 = __ballot_sync(0xffffffffu, nib & 1u);
            const unsigned b1 = __ballot_sync(0xffffffffu, nib & 2u);
            const unsigned b2 = __ballot_sync(0xffffffffu, nib & 4u);
            const unsigned b3 = __ballot_sync(0xffffffffu, nib & 8u);

            const int excl = __popc(b0 & lanemask_lt) + __popc(b1 & lanemask_lt)
                           + __popc(b2 & lanemask_lt) + __popc(b3 & lanemask_lt);
            if (nib) {
                int s = cntA + excl;
                unsigned nb = nib;
                do {
                    const int jj = __ffs(nb) - 1;
                    if (s < BQ_K) sidx[warp][0][s] = bi + jj;
                    s++;
                    nb &= nb - 1u;
                } while (nb);
            }
            cntA += __popc(b0) + __popc(b1) + __popc(b2) + __popc(b3);
        }

        // ---- Chain B ----
        if (cntB < BQ_K) {                               // uniform predicate
            unsigned nib = 0u;
            if (qBsq + m0 - 2.0f * (qBx * x0 + qBy * y0 + qBz * z0) < BQ_R2) nib |= 1u;
            if (qBsq + m1 - 2.0f * (qBx * x1 + qBy * y1 + qBz * z1) < BQ_R2) nib |= 2u;
            if (qBsq + m2 - 2.0f * (qBx * x2 + qBy * y2 + qBz * z2) < BQ_R2) nib |= 4u;
            if (qBsq + m3 - 2.0f * (qBx * x3 + qBy * y3 + qBz * z3) < BQ_R2) nib |= 8u;

            const unsigned b0 = __ballot_sync(0xffffffffu, nib & 1u);
            const unsigned b1 = __ballot_sync(0xffffffffu, nib & 2u);
            const unsigned b2 = __ballot_sync(0xffffffffu, nib & 4u);
            const unsigned b3 = __ballot_sync(0xffffffffu, nib & 8u);

            const int excl = __popc(b0 & lanemask_lt) + __popc(b1 & lanemask_lt)
                           + __popc(b2 & lanemask_lt) + __popc(b3 & lanemask_lt);
            if (nib) {
                int s = cntB + excl;
                unsigned nb = nib;
                do {
                    const int jj = __ffs(nb) - 1;
                    if (s < BQ_K) sidx[warp][1][s] = bi + jj;
                    s++;
                    nb &= nb - 1u;
                } while (nb);
            }
            cntB += __popc(b0) + __popc(b1) + __popc(b2) + __popc(b3);
        }
    }
    __syncwarp();
    // Pad remaining slots with first found index (cnt >= 1: self hit)
    if (lane == 0) {
        const int fA = sidx[warp][0][0];
        for (int j = (cntA < BQ_K ? cntA : BQ_K); j < BQ_K; j++) sidx[warp][0][j] = fA;
        const int fB = sidx[warp][1][0];
        for (int j = (cntB < BQ_K ? cntB : BQ_K); j < BQ_K; j++) sidx[warp][1][j] = fB;
    }
    __syncwarp();

    // ---- Loss for both queries, interleaved (MLP 32) ----
    float acc = 0.0f;
    if (lane < BQ_C) {
        const float* __restrict__ mb = mask + (size_t)b * BQ_N * BQ_C;
        const float mqA = mb[nA * BQ_C + lane];
        const float mqB = mb[nB * BQ_C + lane];
#pragma unroll
        for (int j = 0; j < BQ_K; j++) {
            const int idA = sidx[warp][0][j];
            const int idB = sidx[warp][1][j];
            acc += fabsf(mqA - mb[idA * BQ_C + lane]);
            acc += fabsf(mqB - mb[idB * BQ_C + lane]);
        }
    }
    // Warp reduce (lanes 30,31 contribute 0)
#pragma unroll
    for (int off = 16; off; off >>= 1)
        acc += __shfl_down_sync(0xffffffffu, acc, off);

    __shared__ float wl[WARPS_PER_BLOCK];
    if (lane == 0) wl[warp] = acc;
    __syncthreads();

    // Per-block partial in fixed order (no float atomics -> deterministic)
    __shared__ bool is_last;
    if (threadIdx.x == 0) {
        float s = 0.0f;
#pragma unroll
        for (int w2 = 0; w2 < WARPS_PER_BLOCK; w2++) s += wl[w2];
        g_partials[blockIdx.x] = s;
        __threadfence();                                  // publish partial
        unsigned tk = atomicAdd(&g_ticket, 1u);           // int ticket only
        is_last = (tk == NUM_BLOCKS - 1);
    }
    __syncthreads();

    // ---- Fused final reduction: last block, fixed order, deterministic ----
    if (is_last) {
        __shared__ float sh[256];
        float s = 0.0f;
        for (int i = threadIdx.x; i < NUM_BLOCKS; i += 256)
            s += g_partials[i];
        sh[threadIdx.x] = s;
        __syncthreads();
#pragma unroll
        for (int off = 128; off; off >>= 1) {
            if (threadIdx.x < off) sh[threadIdx.x] += sh[threadIdx.x + off];
            __syncthreads();
        }
        if (threadIdx.x == 0) {
            out[0] = sh[0] * (1.0f / ((float)BQ_K * (float)NUM_QUERIES));
            g_ticket = 0;                                 // reset for next replay
        }
    }
}

extern "C" void kernel_launch(void* const* d_in, const int* in_sizes, int n_in,
                              void* d_out, int out_size) {
    const float* pc   = (const float*)d_in[0];   // (4, 4096, 3) float32
    const float* mask = (const float*)d_in[1];   // (4, 4096, 30) float32
    float* out = (float*)d_out;                  // scalar float32

    ballq_loss_kernel<<<NUM_BLOCKS, WARPS_PER_BLOCK * 32>>>(pc, mask, out);
}